// round 15
// baseline (speedup 1.0000x reference)
#include <cuda_runtime.h>
#include <cuda_fp16.h>
#include <cstdint>
#include <math.h>

#define B_TOK 4096
#define H_DIM 1024
#define C_CAT 64
#define N_SUB 786
#define CN    (C_CAT * N_SUB)   // 50304

#define BM 128
#define BN 128
#define NKC 16                  // K = 1024, single fp16 pass
#define NSTAGE 3
#define NFULL 6                 // full 128-col tiles per category (768 cols)
#define NGRP 10                 // packed tail groups: 9 x 7cats + 1 x 1cat
#define GRIDY (C_CAT * NFULL + NGRP)   // 394
#define NSLOT 7
#define TILE_B 16384            // 128 x 64 fp16
#define STAGE_B (2 * TILE_B)    // 32768
#define BIAS_OFF (NSTAGE * STAGE_B)          // 98304
#define RSUM_OFF (BIAS_OFF + 512)            // 98816
#define SMEM_BYTES (RSUM_OFF + 4 * 128 * 4)  // 100864

#define NSLAB 8
#define RT_SLAB 4               // row tiles per slab
#define B_SLAB (RT_SLAB * 128)  // 512 tokens per slab

// ---------------- device scratch ----------------
__device__ float g_top_probs[B_TOK * C_CAT];                            // 1 MB
__device__ float g_partial[(size_t)B_TOK * C_CAT * 8];                  // 8 MB
__device__ unsigned char g_Abuf[(size_t)32 * NKC * TILE_B];             // 8.4 MB
__device__ unsigned char g_Wbuf[(size_t)C_CAT * NFULL * NKC * TILE_B];  // 100.7 MB
__device__ unsigned char g_Wtail[(size_t)NGRP * NKC * TILE_B];          // 2.6 MB (pads stay 0)

__device__ __forceinline__ uint32_t smem_u32(const void* p) {
    uint32_t a;
    asm("{ .reg .u64 t; cvta.to.shared.u64 t, %1; cvt.u32.u64 %0, t; }" : "=r"(a) : "l"(p));
    return a;
}
__device__ __forceinline__ uint32_t sw128(uint32_t off) { return off ^ ((off >> 3) & 0x70); }

#define CP_ASYNC16(dst, src) \
    asm volatile("cp.async.cg.shared.global [%0], [%1], 16;" :: "r"(dst), "l"(src) : "memory")
#define CP_COMMIT() asm volatile("cp.async.commit_group;" ::: "memory")
#define CP_WAIT1()  asm volatile("cp.async.wait_group 1;" ::: "memory")

#define LDMATRIX_X4(r0, r1, r2, r3, a) \
    asm volatile("ldmatrix.sync.aligned.m8n8.x4.shared.b16 {%0,%1,%2,%3}, [%4];" \
        : "=r"(r0), "=r"(r1), "=r"(r2), "=r"(r3) : "r"(a))

#define MMA16816(c0, c1, c2, c3, a0, a1, a2, a3, b0, b1) \
    asm volatile("mma.sync.aligned.m16n8k16.row.col.f32.f16.f16.f32 " \
        "{%0,%1,%2,%3}, {%4,%5,%6,%7}, {%8,%9}, {%0,%1,%2,%3};" \
        : "+f"(c0), "+f"(c1), "+f"(c2), "+f"(c3) \
        : "r"(a0), "r"(a1), "r"(a2), "r"(a3), "r"(b0), "r"(b1))

// ---------------------------------------------------------------------------
// Kernel 1: top gating softmax
// ---------------------------------------------------------------------------
__global__ void top_kernel(const float* __restrict__ x,
                           const float* __restrict__ Wt,
                           const float* __restrict__ bt)
{
    const int b = blockIdx.x;
    const int t = threadIdx.x;
    __shared__ float sx[H_DIM];
    __shared__ float sl[C_CAT];
    __shared__ float se[C_CAT];
    for (int i = t; i < H_DIM; i += 64) sx[i] = x[b * H_DIM + i];
    __syncthreads();
    float acc = bt[t];
    #pragma unroll 8
    for (int k = 0; k < H_DIM; ++k) acc = fmaf(sx[k], Wt[k * C_CAT + t], acc);
    sl[t] = acc; __syncthreads();
    float mx = -INFINITY;
    #pragma unroll
    for (int i = 0; i < C_CAT; ++i) mx = fmaxf(mx, sl[i]);
    float num = __expf(acc - mx);
    se[t] = num; __syncthreads();
    float s = 0.f;
    #pragma unroll
    for (int i = 0; i < C_CAT; ++i) s += se[i];
    g_top_probs[b * C_CAT + t] = num / s;
}

// ---------------------------------------------------------------------------
// Converter A: x -> swizzled fp16 tiles [rowblk 32][kchunk 16][128x64]
// ---------------------------------------------------------------------------
__global__ void conv_a(const float* __restrict__ x)
{
    const int rb = blockIdx.x;   // 0..31
    const int kc = blockIdx.y;   // 0..15
    const float* src = x + (size_t)rb * 128 * H_DIM + kc * 64;
    unsigned char* dst = g_Abuf + ((size_t)rb * NKC + kc) * TILE_B;
    for (int idx = threadIdx.x; idx < 128 * 32; idx += blockDim.x) {
        int m = idx >> 5, w = idx & 31;
        float2 v = *(const float2*)(src + (size_t)m * H_DIM + w * 2);
        __half2 h = __floats2half2_rn(v.x, v.y);
        *(uint32_t*)(dst + sw128(m * 128 + w * 4)) = *(uint32_t*)&h;
    }
}

// ---------------------------------------------------------------------------
// Converter W: full tiles -> g_Wbuf [c][6][kc][128x64]; tail cols (768..785)
// packed 7 categories per group into g_Wtail [grp][kc] at rows (c%7)*18+j.
// ---------------------------------------------------------------------------
__global__ void conv_w(const float* __restrict__ W)
{
    __shared__ float s[64][129];
    const int kc = blockIdx.x;   // 0..15
    const int nt = blockIdx.y;   // 0..6
    const int c  = blockIdx.z;   // 0..63
    const float* src = W + (size_t)c * H_DIM * N_SUB + (size_t)kc * 64 * N_SUB;
    for (int idx = threadIdx.x; idx < 64 * 128; idx += blockDim.x) {
        int kk = idx >> 7, j = idx & 127;
        int n = nt * 128 + j;
        s[kk][j] = (n < N_SUB) ? src[(size_t)kk * N_SUB + n] : 0.f;
    }
    __syncthreads();
    if (nt < NFULL) {
        unsigned char* dst = g_Wbuf + (((size_t)(c * NFULL + nt)) * NKC + kc) * TILE_B;
        for (int idx = threadIdx.x; idx < 128 * 32; idx += blockDim.x) {
            int n = idx >> 5, w = idx & 31;
            __half2 h = __floats2half2_rn(s[w * 2][n], s[w * 2 + 1][n]);
            *(uint32_t*)(dst + sw128(n * 128 + w * 4)) = *(uint32_t*)&h;
        }
    } else {
        unsigned char* dst = g_Wtail + ((size_t)(c / 7) * NKC + kc) * TILE_B;
        const int rbase = (c % 7) * 18;
        for (int idx = threadIdx.x; idx < 18 * 32; idx += blockDim.x) {
            int j = idx >> 5, w = idx & 31;
            __half2 h = __floats2half2_rn(s[w * 2][j], s[w * 2 + 1][j]);
            *(uint32_t*)(dst + sw128((rbase + j) * 128 + w * 4)) = *(uint32_t*)&h;
        }
    }
}

// ---------------------------------------------------------------------------
// GEMM: CTA = 128 tokens x one n-tile. y<384: full tile (c=y/6, nt=y%6).
// y>=384: packed tail group g=y-384 (7 cats x 18 cols). fp16 mma single pass.
// ---------------------------------------------------------------------------
__global__ void __launch_bounds__(256, 2)
gemm_kernel(const float* __restrict__ bb, float* __restrict__ out, int rt0)
{
    extern __shared__ __align__(128) unsigned char smem[];
    const uint32_t sb = smem_u32(smem);
    const int tid = threadIdx.x, wid = tid >> 5, lane = tid & 31;
    const int warp_m = wid & 1, warp_n = wid >> 1;
    const int rt = blockIdx.x + rt0;
    const bool is_tail = (blockIdx.y >= C_CAT * NFULL);
    const int c  = is_tail ? 0 : blockIdx.y / NFULL;
    const int nt = is_tail ? 0 : blockIdx.y % NFULL;
    const int g  = is_tail ? (blockIdx.y - C_CAT * NFULL) : 0;
    const int ncats = is_tail ? ((g == 9) ? 1 : 7) : 0;

    float* sbias = (float*)(smem + BIAS_OFF);
    float* srsum = (float*)(smem + RSUM_OFF);   // [4][128]
    float* srsum2 = (float*)smem;               // tail: [128][65] after mainloop

    if (is_tail) {
        for (int i = tid; i < BN; i += 256) {
            int cl = i / 18, cin = i - cl * 18;
            sbias[i] = (cl < ncats) ? bb[(7 * g + cl) * N_SUB + 768 + cin] : 0.f;
        }
    } else {
        for (int i = tid; i < BN; i += 256)
            sbias[i] = bb[c * N_SUB + nt * BN + i];
    }

    const unsigned char* Abase = g_Abuf + ((size_t)rt * NKC) * TILE_B;
    const unsigned char* Wbase = is_tail
        ? g_Wtail + ((size_t)g * NKC) * TILE_B
        : g_Wbuf + ((size_t)(c * NFULL + nt) * NKC) * TILE_B;

    auto prefetch = [&](int kc, int s) {
        if (kc < NKC) {
            const unsigned char* As = Abase + (size_t)kc * TILE_B;
            const unsigned char* Ws = Wbase + (size_t)kc * TILE_B;
            uint32_t dA = sb + s * STAGE_B;
            uint32_t dW = dA + TILE_B;
            #pragma unroll
            for (int i = 0; i < 4; ++i) {
                uint32_t off = i * 4096 + tid * 16;
                CP_ASYNC16(dA + off, As + off);
                CP_ASYNC16(dW + off, Ws + off);
            }
        }
        CP_COMMIT();
    };

    prefetch(0, 0);
    prefetch(1, 1);

    float acc[4][4][4];
    #pragma unroll
    for (int i = 0; i < 4; ++i)
        #pragma unroll
        for (int j = 0; j < 4; ++j)
            #pragma unroll
            for (int q = 0; q < 4; ++q) acc[i][j][q] = 0.f;

    const int a_row = warp_m * 64 + (lane & 7) + ((lane >> 3) & 1) * 8;
    const int a_xor = (((lane >> 4) & 1) * 16) ^ ((a_row & 7) << 4);
    const int b_row = warp_n * 32 + (lane & 7) + ((lane >> 4) & 1) * 8;
    const int b_xor = (((lane >> 3) & 1) * 16) ^ ((b_row & 7) << 4);

    for (int kc = 0; kc < NKC; ++kc) {
        CP_WAIT1();
        __syncthreads();
        prefetch(kc + 2, (kc + 2) % NSTAGE);
        const uint32_t aT = sb + (kc % NSTAGE) * STAGE_B;
        const uint32_t wT = aT + TILE_B;
        uint32_t baseA[4], baseB[2];
        #pragma unroll
        for (int mt = 0; mt < 4; ++mt)
            baseA[mt] = aT + (a_row + mt * 16) * 128 + a_xor;
        #pragma unroll
        for (int bt = 0; bt < 2; ++bt)
            baseB[bt] = wT + (b_row + bt * 16) * 128 + b_xor;
        #pragma unroll
        for (int ks = 0; ks < 4; ++ks) {
            const uint32_t kb = ks * 32;
            uint32_t a[4][4], b[2][4];
            #pragma unroll
            for (int mt = 0; mt < 4; ++mt)
                LDMATRIX_X4(a[mt][0], a[mt][1], a[mt][2], a[mt][3], baseA[mt] ^ kb);
            #pragma unroll
            for (int bt = 0; bt < 2; ++bt)
                LDMATRIX_X4(b[bt][0], b[bt][1], b[bt][2], b[bt][3], baseB[bt] ^ kb);
            #pragma unroll
            for (int mt = 0; mt < 4; ++mt)
                #pragma unroll
                for (int ntl = 0; ntl < 4; ++ntl) {
                    uint32_t b0 = b[ntl >> 1][(ntl & 1) * 2];
                    uint32_t b1 = b[ntl >> 1][(ntl & 1) * 2 + 1];
                    MMA16816(acc[mt][ntl][0], acc[mt][ntl][1],
                             acc[mt][ntl][2], acc[mt][ntl][3],
                             a[mt][0], a[mt][1], a[mt][2], a[mt][3], b0, b1);
                }
        }
    }
    __syncthreads();

    const int r_lo = (lane >> 2);
    const int cc_base = warp_n * 32 + (lane & 3) * 2;
    const size_t orows = (size_t)(rt * 128) * CN;

    if (!is_tail) {
        float sum_lo[4], sum_hi[4];
        #pragma unroll
        for (int mt = 0; mt < 4; ++mt) { sum_lo[mt] = 0.f; sum_hi[mt] = 0.f; }
        const size_t orow0 = orows + (size_t)c * N_SUB + (size_t)nt * BN;

        #pragma unroll
        for (int mt = 0; mt < 4; ++mt) {
            const int row_lo = warp_m * 64 + mt * 16 + r_lo;
            const int row_hi = row_lo + 8;
            #pragma unroll
            for (int ntl = 0; ntl < 4; ++ntl) {
                const int cc = cc_base + ntl * 8;
                float e0 = __expf(acc[mt][ntl][0] + sbias[cc]);
                float e1 = __expf(acc[mt][ntl][1] + sbias[cc + 1]);
                sum_lo[mt] += e0 + e1;
                *(float2*)&out[orow0 + (size_t)row_lo * CN + cc] = make_float2(e0, e1);
                float e2 = __expf(acc[mt][ntl][2] + sbias[cc]);
                float e3 = __expf(acc[mt][ntl][3] + sbias[cc + 1]);
                sum_hi[mt] += e2 + e3;
                *(float2*)&out[orow0 + (size_t)row_hi * CN + cc] = make_float2(e2, e3);
            }
        }
        #pragma unroll
        for (int mt = 0; mt < 4; ++mt) {
            #pragma unroll
            for (int o = 1; o <= 2; o <<= 1) {
                sum_lo[mt] += __shfl_xor_sync(0xFFFFFFFFu, sum_lo[mt], o);
                sum_hi[mt] += __shfl_xor_sync(0xFFFFFFFFu, sum_hi[mt], o);
            }
        }
        if ((lane & 3) == 0) {
            #pragma unroll
            for (int mt = 0; mt < 4; ++mt) {
                srsum[warp_n * 128 + warp_m * 64 + mt * 16 + r_lo]     = sum_lo[mt];
                srsum[warp_n * 128 + warp_m * 64 + mt * 16 + r_lo + 8] = sum_hi[mt];
            }
        }
        __syncthreads();
        if (tid < 128) {
            float tot = srsum[tid] + srsum[128 + tid] + srsum[256 + tid] + srsum[384 + tid];
            g_partial[((size_t)(rt * 128 + tid) * C_CAT + c) * 8 + nt] = tot;
        }
    } else {
        const int nvcols = ncats * 18;
        #pragma unroll
        for (int mt = 0; mt < 4; ++mt) {
            const int row_lo = warp_m * 64 + mt * 16 + r_lo;
            const int row_hi = row_lo + 8;
            #pragma unroll
            for (int ntl = 0; ntl < 4; ++ntl) {
                const int cc = cc_base + ntl * 8;
                const bool v = (cc + 1) < nvcols;
                const int cat = cc / 18, cin = cc - cat * 18;
                const size_t ob = orows + (size_t)(7 * g + cat) * N_SUB + 768 + cin;
                float e0 = 0.f, e1 = 0.f, e2 = 0.f, e3 = 0.f;
                if (v) {
                    e0 = __expf(acc[mt][ntl][0] + sbias[cc]);
                    e1 = __expf(acc[mt][ntl][1] + sbias[cc + 1]);
                    e2 = __expf(acc[mt][ntl][2] + sbias[cc]);
                    e3 = __expf(acc[mt][ntl][3] + sbias[cc + 1]);
                    *(float2*)&out[ob + (size_t)row_lo * CN] = make_float2(e0, e1);
                    *(float2*)&out[ob + (size_t)row_hi * CN] = make_float2(e2, e3);
                }
                const int pidx = warp_n * 16 + ntl * 4 + (lane & 3);
                srsum2[row_lo * 65 + pidx] = e0 + e1;
                srsum2[row_hi * 65 + pidx] = e2 + e3;
            }
        }
        __syncthreads();
        if (tid < 128) {
            for (int cl = 0; cl < ncats; ++cl) {
                float s = 0.f;
                #pragma unroll
                for (int p = 0; p < 9; ++p) s += srsum2[tid * 65 + cl * 9 + p];
                g_partial[((size_t)(rt * 128 + tid) * C_CAT + 7 * g + cl) * 8 + 6] = s;
            }
        }
    }
}

// ---------------------------------------------------------------------------
// Finalize (per slab): out *= gate / sum(partials), deterministic order.
// ---------------------------------------------------------------------------
__global__ void finalize_kernel(float* __restrict__ out, int b0)
{
    const int b = blockIdx.x + b0;
    const int c = blockIdx.y;
    const float* p = &g_partial[((size_t)b * C_CAT + c) * 8];
    float tot = 0.f;
    #pragma unroll
    for (int t = 0; t < NSLOT; ++t) tot += p[t];
    const float scale = g_top_probs[b * C_CAT + c] / tot;
    float2* row = (float2*)(out + (size_t)b * CN + (size_t)c * N_SUB);
    for (int j = threadIdx.x; j < N_SUB / 2; j += blockDim.x) {
        float2 v = row[j];
        v.x *= scale; v.y *= scale;
        row[j] = v;
    }
}

// ---------------------------------------------------------------------------
extern "C" void kernel_launch(void* const* d_in, const int* in_sizes, int n_in,
                              void* d_out, int out_size)
{
    const float* x  = (const float*)d_in[0];   // [B, H]
    const float* Wt = (const float*)d_in[1];   // [H, C]
    const float* bt = (const float*)d_in[2];   // [C]
    const float* Wb = (const float*)d_in[3];   // [C, H, N]
    const float* bb = (const float*)d_in[4];   // [C, N]
    float* out = (float*)d_out;

    static cudaStream_t s2 = nullptr;
    static cudaEvent_t ev0, evA, evF[NSLAB], evJ[NSLAB];
    if (!s2) {
        cudaStreamCreateWithFlags(&s2, cudaStreamNonBlocking);
        cudaEventCreateWithFlags(&ev0, cudaEventDisableTiming);
        cudaEventCreateWithFlags(&evA, cudaEventDisableTiming);
        for (int i = 0; i < NSLAB; ++i) {
            cudaEventCreateWithFlags(&evF[i], cudaEventDisableTiming);
            cudaEventCreateWithFlags(&evJ[i], cudaEventDisableTiming);
        }
    }

    cudaFuncSetAttribute(gemm_kernel, cudaFuncAttributeMaxDynamicSharedMemorySize, SMEM_BYTES);

    // fork: conv_a + top gating on s2, conv_w on stream 0 (concurrent)
    cudaEventRecord(ev0, 0);
    cudaStreamWaitEvent(s2, ev0, 0);
    conv_a<<<dim3(32, NKC), 256, 0, s2>>>(x);
    top_kernel<<<B_TOK, 64, 0, s2>>>(x, Wt, bt);
    cudaEventRecord(evA, s2);

    conv_w<<<dim3(NKC, 7, C_CAT), 256>>>(Wb);
    cudaStreamWaitEvent(0, evA, 0);      // gemm needs conv_a output

    // Slabbed gemm on stream 0; per-slab finalize forked onto s2.
    for (int s = 0; s < NSLAB; ++s) {
        gemm_kernel<<<dim3(RT_SLAB, GRIDY), 256, SMEM_BYTES>>>(bb, out, s * RT_SLAB);
        cudaEventRecord(evF[s], 0);
        cudaStreamWaitEvent(s2, evF[s], 0);
        finalize_kernel<<<dim3(B_SLAB, C_CAT), 128, 0, s2>>>(out, s * B_SLAB);
        cudaEventRecord(evJ[s], s2);
    }
    for (int s = 0; s < NSLAB; ++s)
        cudaStreamWaitEvent(0, evJ[s], 0);
}

// round 17
// speedup vs baseline: 1.0178x; 1.0178x over previous
#include <cuda_runtime.h>
#include <cuda_fp16.h>
#include <cstdint>
#include <math.h>

#define B_TOK 4096
#define H_DIM 1024
#define C_CAT 64
#define N_SUB 786
#define CN    (C_CAT * N_SUB)   // 50304

#define BM 128
#define BN 128
#define NKC 16                  // K = 1024, single fp16 pass
#define NSTAGE 3
#define NFULL 6                 // full 128-col tiles per category (768 cols)
#define NGRP 10                 // packed tail groups: 9 x 7cats + 1 x 1cat
#define GRIDY (C_CAT * NFULL + NGRP)   // 394
#define NSLOT 7
#define TILE_B 16384            // 128 x 64 fp16
#define STAGE_B (2 * TILE_B)    // 32768
#define BIAS_OFF (NSTAGE * STAGE_B)          // 98304
#define RSUM_OFF (BIAS_OFF + 512)            // 98816
#define SMEM_BYTES (RSUM_OFF + 2 * 128 * 4)  // 99840

#define NSLAB 8
#define RT_SLAB 4               // row tiles per slab
#define B_SLAB (RT_SLAB * 128)  // 512 tokens per slab

// ---------------- device scratch ----------------
__device__ float g_top_probs[B_TOK * C_CAT];                            // 1 MB
__device__ float g_partial[(size_t)B_TOK * C_CAT * 8];                  // 8 MB
__device__ unsigned char g_Abuf[(size_t)32 * NKC * TILE_B];             // 8.4 MB
__device__ unsigned char g_Wbuf[(size_t)C_CAT * NFULL * NKC * TILE_B];  // 100.7 MB
__device__ unsigned char g_Wtail[(size_t)NGRP * NKC * TILE_B];          // 2.6 MB (pads stay 0)

__device__ __forceinline__ uint32_t smem_u32(const void* p) {
    uint32_t a;
    asm("{ .reg .u64 t; cvta.to.shared.u64 t, %1; cvt.u32.u64 %0, t; }" : "=r"(a) : "l"(p));
    return a;
}
__device__ __forceinline__ uint32_t sw128(uint32_t off) { return off ^ ((off >> 3) & 0x70); }

#define CP_ASYNC16(dst, src) \
    asm volatile("cp.async.cg.shared.global [%0], [%1], 16;" :: "r"(dst), "l"(src) : "memory")
#define CP_COMMIT() asm volatile("cp.async.commit_group;" ::: "memory")
#define CP_WAIT1()  asm volatile("cp.async.wait_group 1;" ::: "memory")

#define LDMATRIX_X4(r0, r1, r2, r3, a) \
    asm volatile("ldmatrix.sync.aligned.m8n8.x4.shared.b16 {%0,%1,%2,%3}, [%4];" \
        : "=r"(r0), "=r"(r1), "=r"(r2), "=r"(r3) : "r"(a))

#define MMA16816(c0, c1, c2, c3, a0, a1, a2, a3, b0, b1) \
    asm volatile("mma.sync.aligned.m16n8k16.row.col.f32.f16.f16.f32 " \
        "{%0,%1,%2,%3}, {%4,%5,%6,%7}, {%8,%9}, {%0,%1,%2,%3};" \
        : "+f"(c0), "+f"(c1), "+f"(c2), "+f"(c3) \
        : "r"(a0), "r"(a1), "r"(a2), "r"(a3), "r"(b0), "r"(b1))

// ---------------------------------------------------------------------------
// Kernel 1: top gating softmax
// ---------------------------------------------------------------------------
__global__ void top_kernel(const float* __restrict__ x,
                           const float* __restrict__ Wt,
                           const float* __restrict__ bt)
{
    const int b = blockIdx.x;
    const int t = threadIdx.x;
    __shared__ float sx[H_DIM];
    __shared__ float sl[C_CAT];
    __shared__ float se[C_CAT];
    for (int i = t; i < H_DIM; i += 64) sx[i] = x[b * H_DIM + i];
    __syncthreads();
    float acc = bt[t];
    #pragma unroll 8
    for (int k = 0; k < H_DIM; ++k) acc = fmaf(sx[k], Wt[k * C_CAT + t], acc);
    sl[t] = acc; __syncthreads();
    float mx = -INFINITY;
    #pragma unroll
    for (int i = 0; i < C_CAT; ++i) mx = fmaxf(mx, sl[i]);
    float num = __expf(acc - mx);
    se[t] = num; __syncthreads();
    float s = 0.f;
    #pragma unroll
    for (int i = 0; i < C_CAT; ++i) s += se[i];
    g_top_probs[b * C_CAT + t] = num / s;
}

// ---------------------------------------------------------------------------
// Converter A: x -> swizzled fp16 tiles [rowblk 32][kchunk 16][128x64]
// ---------------------------------------------------------------------------
__global__ void conv_a(const float* __restrict__ x)
{
    const int rb = blockIdx.x;   // 0..31
    const int kc = blockIdx.y;   // 0..15
    const float* src = x + (size_t)rb * 128 * H_DIM + kc * 64;
    unsigned char* dst = g_Abuf + ((size_t)rb * NKC + kc) * TILE_B;
    for (int idx = threadIdx.x; idx < 128 * 32; idx += blockDim.x) {
        int m = idx >> 5, w = idx & 31;
        float2 v = *(const float2*)(src + (size_t)m * H_DIM + w * 2);
        __half2 h = __floats2half2_rn(v.x, v.y);
        *(uint32_t*)(dst + sw128(m * 128 + w * 4)) = *(uint32_t*)&h;
    }
}

// ---------------------------------------------------------------------------
// Converter W: full tiles -> g_Wbuf [c][6][kc][128x64]; tail cols (768..785)
// packed 7 categories per group into g_Wtail [grp][kc] at rows (c%7)*18+j.
// ---------------------------------------------------------------------------
__global__ void conv_w(const float* __restrict__ W)
{
    __shared__ float s[64][129];
    const int kc = blockIdx.x;   // 0..15
    const int nt = blockIdx.y;   // 0..6
    const int c  = blockIdx.z;   // 0..63
    const float* src = W + (size_t)c * H_DIM * N_SUB + (size_t)kc * 64 * N_SUB;
    for (int idx = threadIdx.x; idx < 64 * 128; idx += blockDim.x) {
        int kk = idx >> 7, j = idx & 127;
        int n = nt * 128 + j;
        s[kk][j] = (n < N_SUB) ? src[(size_t)kk * N_SUB + n] : 0.f;
    }
    __syncthreads();
    if (nt < NFULL) {
        unsigned char* dst = g_Wbuf + (((size_t)(c * NFULL + nt)) * NKC + kc) * TILE_B;
        for (int idx = threadIdx.x; idx < 128 * 32; idx += blockDim.x) {
            int n = idx >> 5, w = idx & 31;
            __half2 h = __floats2half2_rn(s[w * 2][n], s[w * 2 + 1][n]);
            *(uint32_t*)(dst + sw128(n * 128 + w * 4)) = *(uint32_t*)&h;
        }
    } else {
        unsigned char* dst = g_Wtail + ((size_t)(c / 7) * NKC + kc) * TILE_B;
        const int rbase = (c % 7) * 18;
        for (int idx = threadIdx.x; idx < 18 * 32; idx += blockDim.x) {
            int j = idx >> 5, w = idx & 31;
            __half2 h = __floats2half2_rn(s[w * 2][j], s[w * 2 + 1][j]);
            *(uint32_t*)(dst + sw128((rbase + j) * 128 + w * 4)) = *(uint32_t*)&h;
        }
    }
}

// ---------------------------------------------------------------------------
// GEMM: CTA = 128 tokens x one n-tile, 128 threads / 4 warps, each warp
// owns m64 x n64 (2x2 warp grid) -> smem reads cut 33% vs 2x4 grid.
// y<384: full tile (c=y/6, nt=y%6). y>=384: packed tail group g=y-384.
// ---------------------------------------------------------------------------
__global__ void __launch_bounds__(128, 2)
gemm_kernel(const float* __restrict__ bb, float* __restrict__ out, int rt0)
{
    extern __shared__ __align__(128) unsigned char smem[];
    const uint32_t sb = smem_u32(smem);
    const int tid = threadIdx.x, wid = tid >> 5, lane = tid & 31;
    const int warp_m = wid & 1, warp_n = wid >> 1;      // 2x2
    const int rt = blockIdx.x + rt0;
    const bool is_tail = (blockIdx.y >= C_CAT * NFULL);
    const int c  = is_tail ? 0 : blockIdx.y / NFULL;
    const int nt = is_tail ? 0 : blockIdx.y % NFULL;
    const int g  = is_tail ? (blockIdx.y - C_CAT * NFULL) : 0;
    const int ncats = is_tail ? ((g == 9) ? 1 : 7) : 0;

    float* sbias = (float*)(smem + BIAS_OFF);
    float* srsum = (float*)(smem + RSUM_OFF);   // [2][128]
    float* srsum2 = (float*)smem;               // tail: [128][65] after mainloop

    if (is_tail) {
        for (int i = tid; i < BN; i += 128) {
            int cl = i / 18, cin = i - cl * 18;
            sbias[i] = (cl < ncats) ? bb[(7 * g + cl) * N_SUB + 768 + cin] : 0.f;
        }
    } else {
        for (int i = tid; i < BN; i += 128)
            sbias[i] = bb[c * N_SUB + nt * BN + i];
    }

    const unsigned char* Abase = g_Abuf + ((size_t)rt * NKC) * TILE_B;
    const unsigned char* Wbase = is_tail
        ? g_Wtail + ((size_t)g * NKC) * TILE_B
        : g_Wbuf + ((size_t)(c * NFULL + nt) * NKC) * TILE_B;

    auto prefetch = [&](int kc, int s) {
        if (kc < NKC) {
            const unsigned char* As = Abase + (size_t)kc * TILE_B;
            const unsigned char* Ws = Wbase + (size_t)kc * TILE_B;
            uint32_t dA = sb + s * STAGE_B;
            uint32_t dW = dA + TILE_B;
            #pragma unroll
            for (int i = 0; i < 8; ++i) {
                uint32_t off = i * 2048 + tid * 16;
                CP_ASYNC16(dA + off, As + off);
                CP_ASYNC16(dW + off, Ws + off);
            }
        }
        CP_COMMIT();
    };

    prefetch(0, 0);
    prefetch(1, 1);

    float acc[4][8][4];
    #pragma unroll
    for (int i = 0; i < 4; ++i)
        #pragma unroll
        for (int j = 0; j < 8; ++j)
            #pragma unroll
            for (int q = 0; q < 4; ++q) acc[i][j][q] = 0.f;

    // XOR-folded ldmatrix addressing
    const int a_row = warp_m * 64 + (lane & 7) + ((lane >> 3) & 1) * 8;   // + mt*16
    const int a_xor = (((lane >> 4) & 1) * 16) ^ ((a_row & 7) << 4);
    const int b_row = warp_n * 64 + (lane & 7) + ((lane >> 4) & 1) * 8;   // + bt*16
    const int b_xor = (((lane >> 3) & 1) * 16) ^ ((b_row & 7) << 4);

    for (int kc = 0; kc < NKC; ++kc) {
        CP_WAIT1();
        __syncthreads();
        prefetch(kc + 2, (kc + 2) % NSTAGE);
        const uint32_t aT = sb + (kc % NSTAGE) * STAGE_B;
        const uint32_t wT = aT + TILE_B;
        uint32_t baseA[4], baseB[4];
        #pragma unroll
        for (int mt = 0; mt < 4; ++mt)
            baseA[mt] = aT + (a_row + mt * 16) * 128 + a_xor;
        #pragma unroll
        for (int bt = 0; bt < 4; ++bt)
            baseB[bt] = wT + (b_row + bt * 16) * 128 + b_xor;
        #pragma unroll
        for (int ks = 0; ks < 4; ++ks) {
            const uint32_t kb = ks * 32;
            uint32_t a[4][4], b[4][4];
            #pragma unroll
            for (int mt = 0; mt < 4; ++mt)
                LDMATRIX_X4(a[mt][0], a[mt][1], a[mt][2], a[mt][3], baseA[mt] ^ kb);
            #pragma unroll
            for (int bt = 0; bt < 4; ++bt)
                LDMATRIX_X4(b[bt][0], b[bt][1], b[bt][2], b[bt][3], baseB[bt] ^ kb);
            #pragma unroll
            for (int mt = 0; mt < 4; ++mt)
                #pragma unroll
                for (int ntl = 0; ntl < 8; ++ntl) {
                    uint32_t b0 = b[ntl >> 1][(ntl & 1) * 2];
                    uint32_t b1 = b[ntl >> 1][(ntl & 1) * 2 + 1];
                    MMA16816(acc[mt][ntl][0], acc[mt][ntl][1],
                             acc[mt][ntl][2], acc[mt][ntl][3],
                             a[mt][0], a[mt][1], a[mt][2], a[mt][3], b0, b1);
                }
        }
    }
    __syncthreads();

    const int r_lo = (lane >> 2);
    const int cc_base = warp_n * 64 + (lane & 3) * 2;
    const size_t orows = (size_t)(rt * 128) * CN;

    if (!is_tail) {
        float sum_lo[4], sum_hi[4];
        #pragma unroll
        for (int mt = 0; mt < 4; ++mt) { sum_lo[mt] = 0.f; sum_hi[mt] = 0.f; }
        const size_t orow0 = orows + (size_t)c * N_SUB + (size_t)nt * BN;

        #pragma unroll
        for (int mt = 0; mt < 4; ++mt) {
            const int row_lo = warp_m * 64 + mt * 16 + r_lo;
            const int row_hi = row_lo + 8;
            #pragma unroll
            for (int ntl = 0; ntl < 8; ++ntl) {
                const int cc = cc_base + ntl * 8;
                float e0 = __expf(acc[mt][ntl][0] + sbias[cc]);
                float e1 = __expf(acc[mt][ntl][1] + sbias[cc + 1]);
                sum_lo[mt] += e0 + e1;
                *(float2*)&out[orow0 + (size_t)row_lo * CN + cc] = make_float2(e0, e1);
                float e2 = __expf(acc[mt][ntl][2] + sbias[cc]);
                float e3 = __expf(acc[mt][ntl][3] + sbias[cc + 1]);
                sum_hi[mt] += e2 + e3;
                *(float2*)&out[orow0 + (size_t)row_hi * CN + cc] = make_float2(e2, e3);
            }
        }
        #pragma unroll
        for (int mt = 0; mt < 4; ++mt) {
            #pragma unroll
            for (int o = 1; o <= 2; o <<= 1) {
                sum_lo[mt] += __shfl_xor_sync(0xFFFFFFFFu, sum_lo[mt], o);
                sum_hi[mt] += __shfl_xor_sync(0xFFFFFFFFu, sum_hi[mt], o);
            }
        }
        if ((lane & 3) == 0) {
            #pragma unroll
            for (int mt = 0; mt < 4; ++mt) {
                srsum[warp_n * 128 + warp_m * 64 + mt * 16 + r_lo]     = sum_lo[mt];
                srsum[warp_n * 128 + warp_m * 64 + mt * 16 + r_lo + 8] = sum_hi[mt];
            }
        }
        __syncthreads();
        {
            float tot = srsum[tid] + srsum[128 + tid];
            g_partial[((size_t)(rt * 128 + tid) * C_CAT + c) * 8 + nt] = tot;
        }
    } else {
        const int nvcols = ncats * 18;
        #pragma unroll
        for (int mt = 0; mt < 4; ++mt) {
            const int row_lo = warp_m * 64 + mt * 16 + r_lo;
            const int row_hi = row_lo + 8;
            #pragma unroll
            for (int ntl = 0; ntl < 8; ++ntl) {
                const int cc = cc_base + ntl * 8;
                const bool v = (cc + 1) < nvcols;
                const int cat = cc / 18, cin = cc - cat * 18;
                const size_t ob = orows + (size_t)(7 * g + cat) * N_SUB + 768 + cin;
                float e0 = 0.f, e1 = 0.f, e2 = 0.f, e3 = 0.f;
                if (v) {
                    e0 = __expf(acc[mt][ntl][0] + sbias[cc]);
                    e1 = __expf(acc[mt][ntl][1] + sbias[cc + 1]);
                    e2 = __expf(acc[mt][ntl][2] + sbias[cc]);
                    e3 = __expf(acc[mt][ntl][3] + sbias[cc + 1]);
                    *(float2*)&out[ob + (size_t)row_lo * CN] = make_float2(e0, e1);
                    *(float2*)&out[ob + (size_t)row_hi * CN] = make_float2(e2, e3);
                }
                const int pidx = cc >> 1;          // 0..63
                srsum2[row_lo * 65 + pidx] = e0 + e1;
                srsum2[row_hi * 65 + pidx] = e2 + e3;
            }
        }
        __syncthreads();
        {
            for (int cl = 0; cl < ncats; ++cl) {
                float s = 0.f;
                #pragma unroll
                for (int p = 0; p < 9; ++p) s += srsum2[tid * 65 + cl * 9 + p];
                g_partial[((size_t)(rt * 128 + tid) * C_CAT + 7 * g + cl) * 8 + 6] = s;
            }
        }
    }
}

// ---------------------------------------------------------------------------
// Finalize (per slab): out *= gate / sum(partials), deterministic order.
// ---------------------------------------------------------------------------
__global__ void finalize_kernel(float* __restrict__ out, int b0)
{
    const int b = blockIdx.x + b0;
    const int c = blockIdx.y;
    const float* p = &g_partial[((size_t)b * C_CAT + c) * 8];
    float tot = 0.f;
    #pragma unroll
    for (int t = 0; t < NSLOT; ++t) tot += p[t];
    const float scale = g_top_probs[b * C_CAT + c] / tot;
    float2* row = (float2*)(out + (size_t)b * CN + (size_t)c * N_SUB);
    for (int j = threadIdx.x; j < N_SUB / 2; j += blockDim.x) {
        float2 v = row[j];
        v.x *= scale; v.y *= scale;
        row[j] = v;
    }
}

// ---------------------------------------------------------------------------
extern "C" void kernel_launch(void* const* d_in, const int* in_sizes, int n_in,
                              void* d_out, int out_size)
{
    const float* x  = (const float*)d_in[0];   // [B, H]
    const float* Wt = (const float*)d_in[1];   // [H, C]
    const float* bt = (const float*)d_in[2];   // [C]
    const float* Wb = (const float*)d_in[3];   // [C, H, N]
    const float* bb = (const float*)d_in[4];   // [C, N]
    float* out = (float*)d_out;

    static cudaStream_t s2 = nullptr;
    static cudaEvent_t ev0, evA, evF[NSLAB], evJ[NSLAB];
    if (!s2) {
        cudaStreamCreateWithFlags(&s2, cudaStreamNonBlocking);
        cudaEventCreateWithFlags(&ev0, cudaEventDisableTiming);
        cudaEventCreateWithFlags(&evA, cudaEventDisableTiming);
        for (int i = 0; i < NSLAB; ++i) {
            cudaEventCreateWithFlags(&evF[i], cudaEventDisableTiming);
            cudaEventCreateWithFlags(&evJ[i], cudaEventDisableTiming);
        }
    }

    cudaFuncSetAttribute(gemm_kernel, cudaFuncAttributeMaxDynamicSharedMemorySize, SMEM_BYTES);

    // fork: conv_a + top gating on s2, conv_w on stream 0 (concurrent)
    cudaEventRecord(ev0, 0);
    cudaStreamWaitEvent(s2, ev0, 0);
    conv_a<<<dim3(32, NKC), 256, 0, s2>>>(x);
    top_kernel<<<B_TOK, 64, 0, s2>>>(x, Wt, bt);
    cudaEventRecord(evA, s2);

    conv_w<<<dim3(NKC, 7, C_CAT), 256>>>(Wb);
    cudaStreamWaitEvent(0, evA, 0);      // gemm needs conv_a output

    // Slabbed gemm on stream 0; per-slab finalize forked onto s2.
    for (int s = 0; s < NSLAB; ++s) {
        gemm_kernel<<<dim3(RT_SLAB, GRIDY), 128, SMEM_BYTES>>>(bb, out, s * RT_SLAB);
        cudaEventRecord(evF[s], 0);
        cudaStreamWaitEvent(s2, evF[s], 0);
        finalize_kernel<<<dim3(B_SLAB, C_CAT), 128, 0, s2>>>(out, s * B_SLAB);
        cudaEventRecord(evJ[s], s2);
    }
    for (int s = 0; s < NSLAB; ++s)
        cudaStreamWaitEvent(0, evJ[s], 0);
}